// round 6
// baseline (speedup 1.0000x reference)
#include <cuda_runtime.h>

#define NF 36
#define NO 1000
#define NT 256
#define NC 81

// ---------------------------------------------------------------------------
// A) Fused softmax + class cost. Block owns 2 o's x all 256 t's.
//    Logits loaded as LDG.128 (rows are 324B, 4B-aligned only -> load from the
//    row's 16B-aligned floor, predicate the 84-float window down to 81).
//    3 rows per warp in flight -> 4x outstanding bytes vs scalar loads.
//    Initializes d_out with class term + the GIoU "+1" constant.
// ---------------------------------------------------------------------------
__global__ __launch_bounds__(256) void class_kernel(
    const float* __restrict__ logits,  // [F*O, C]
    const int*   __restrict__ tgt_ids, // [T*F]
    float*       __restrict__ out)     // [O, T]
{
    __shared__ float2 s_prob2[NF][NC];        // 23328 B
    __shared__ int    s_id4[NT][NF / 4];      // 9216 B

    const int ob   = blockIdx.x * 2;
    const int tid  = threadIdx.x;
    const int warp = tid >> 5;
    const int lane = tid & 31;

    // ---- pack ids: 4 consecutive frames per int (class < 81 < 256) ----
    const int4* ids4 = (const int4*)tgt_ids;
    for (int i = tid; i < NT * NF / 4; i += 256) {
        int4 q = ids4[i];
        int t = i / (NF / 4);
        int p = i - t * (NF / 4);
        s_id4[t][p] = (q.x) | (q.y << 8) | (q.z << 16) | (q.w << 24);
    }

    // ---- softmax: 72 rows, 9 per warp, batches of 3 (3 LDG.128 in flight) --
    const bool act = (lane < 21);   // 21 float4 = 84 floats cover 81 + align
    #pragma unroll
    for (int rb = 0; rb < 9; rb += 3) {
        float4 v[3];
        int off[3], fr[3], olr[3];
        #pragma unroll
        for (int k = 0; k < 3; k++) {
            int row = warp + 8 * (rb + k);        // 0..71
            int ol  = row / NF;
            int f   = row - ol * NF;
            fr[k] = f; olr[k] = ol;
            int start = (f * NO + ob + ol) * NC;  // first elem of this row
            int a = start & 3;                    // misalignment in elems
            off[k] = a;
            const float4* base = (const float4*)(logits + (start - a));
            if (act) v[k] = base[lane];
        }
        float e[3][4], s[3];
        #pragma unroll
        for (int k = 0; k < 3; k++) {
            float vv[4] = {v[k].x, v[k].y, v[k].z, v[k].w};
            s[k] = 0.0f;
            #pragma unroll
            for (int j = 0; j < 4; j++) {
                int c = 4 * lane + j - off[k];
                bool valid = act && ((unsigned)c < NC);
                e[k][j] = valid ? __expf(vv[j]) : 0.0f;   // max-free: logits O(1)
                s[k] += e[k][j];
            }
        }
        #pragma unroll
        for (int st = 16; st; st >>= 1) {
            #pragma unroll
            for (int k = 0; k < 3; k++)
                s[k] += __shfl_xor_sync(0xffffffffu, s[k], st);
        }
        #pragma unroll
        for (int k = 0; k < 3; k++) {
            float inv = __frcp_rn(s[k]);
            #pragma unroll
            for (int j = 0; j < 4; j++) {
                int c = 4 * lane + j - off[k];
                if (act && ((unsigned)c < NC))
                    ((float*)&s_prob2[fr[k]][c])[olr[k]] = e[k][j] * inv;
            }
        }
    }
    __syncthreads();

    // ---- gather: one LDS.64 covers both o's ----
    const int t = tid;
    float a0 = 0.0f, a1 = 0.0f;
    #pragma unroll
    for (int fq = 0; fq < NF / 4; fq++) {
        int packed = s_id4[t][fq];
        #pragma unroll
        for (int b = 0; b < 4; b++) {
            int c = (packed >> (8 * b)) & 0xFF;
            float2 pr = s_prob2[fq * 4 + b][c];
            a0 += pr.x;
            a1 += pr.y;
        }
    }
    out[(ob + 0) * NT + t] = 1.0f - a0 * (1.0f / NF);
    out[(ob + 1) * NT + t] = 1.0f - a1 * (1.0f / NF);
}

// ---------------------------------------------------------------------------
// B) Box cost: block = 16 o x 16 t (256 thr, 1 output/thread, 1008 blocks).
//    Warp covers 16 t x 2 o with ADJACENT LANES SHARING t -> the T-tile LDS
//    dedups to 16 addresses (2 wavefronts instead of 4); P is a 2-address
//    broadcast. Explicit P/T prefetch pipelines the 29-cyc LDS latency.
// ---------------------------------------------------------------------------
__global__ __launch_bounds__(256) void box_kernel(
    const float4* __restrict__ pred_boxes,   // [F, O] cxcywh
    const float4* __restrict__ tgt_bbox,     // [T, F] cxcywh
    float*        __restrict__ out)          // [O, T]
{
    __shared__ float4 s_pred[16][NF];    // xyxy 9216 B
    __shared__ float4 s_tgt[NF][16];     // xyxy 9216 B

    const int ob  = blockIdx.y * 16;
    const int tb  = blockIdx.x * 16;
    const int tid = threadIdx.x;

    for (int i = tid; i < 16 * NF; i += 256) {
        int ol = i & 15, f = i >> 4;
        int o  = min(ob + ol, NO - 1);            // clamp ragged last o-tile
        float4 b = pred_boxes[f * NO + o];
        s_pred[ol][f] = make_float4(b.x - 0.5f * b.z, b.y - 0.5f * b.w,
                                    b.x + 0.5f * b.z, b.y + 0.5f * b.w);
    }
    for (int i = tid; i < 16 * NF; i += 256) {
        int tl = i / NF, f = i - tl * NF;
        float4 b = tgt_bbox[(tb + tl) * NF + f];
        s_tgt[f][tl] = make_float4(b.x - 0.5f * b.z, b.y - 0.5f * b.w,
                                   b.x + 0.5f * b.z, b.y + 0.5f * b.w);
    }
    __syncthreads();

    const int lane = tid & 31;
    const int wid  = tid >> 5;
    const int op   = lane & 1;        // which of the warp's 2 o's
    const int tl   = lane >> 1;       // t within tile (adjacent lanes share)
    const int ol   = 2 * wid + op;    // o within tile

    float accG  = 0.0f;
    float accCx = 0.0f, accCy = 0.0f;   // |dx0+dx1|, |dy0+dy1| (center terms)
    float accBx = 0.0f, accBy = 0.0f;   // |dx1-dx0|, |dy1-dy0| (w/h terms)

    float4 P = s_pred[ol][0];
    float4 T = s_tgt[0][tl];

    #pragma unroll 4
    for (int f = 0; f < NF; f++) {
        float4 Pn, Tn;
        if (f < NF - 1) {                 // prefetch next frame
            Pn = s_pred[ol][f + 1];
            Tn = s_tgt[f + 1][tl];
        }

        float pw = P.z - P.x, ph = P.w - P.y;
        float tw = T.z - T.x, th = T.w - T.y;

        float iw = fminf(P.z, T.z) - fmaxf(P.x, T.x);
        float ih = fminf(P.w, T.w) - fmaxf(P.y, T.y);
        float inter = fmaxf(iw, 0.0f) * fmaxf(ih, 0.0f);
        float uni = fmaf(pw, ph, tw * th) - inter;
        float ca  = ((pw + tw) - iw) * ((ph + th) - ih);

        // inter/uni + uni/ca = (inter*ca + uni*uni) / (uni*ca)
        float r = __frcp_rn(uni * ca);
        accG = fmaf(fmaf(inter, ca, uni * uni), r, accG);

        float dx0 = P.x - T.x, dx1 = P.z - T.z;
        float dy0 = P.y - T.y, dy1 = P.w - T.w;
        accCx += fabsf(dx0 + dx1);
        accCy += fabsf(dy0 + dy1);
        accBx += fabsf(dx1 - dx0);
        accBy += fabsf(dy1 - dy0);

        P = Pn; T = Tn;
    }

    int o = ob + ol;
    int t = tb + tl;
    if (o < NO) {
        // bbox = (0.5*(accCx+accCy) + accBx+accBy)/(NF*4);
        // giou "+1" constant was folded into class_kernel's init.
        out[o * NT + t] += (0.5f * (accCx + accCy) + accBx + accBy) * (1.0f / (NF * 4))
                           - accG * (1.0f / NF);
    }
}

// ---------------------------------------------------------------------------
extern "C" void kernel_launch(void* const* d_in, const int* in_sizes, int n_in,
                              void* d_out, int out_size) {
    const float* pred_logits = (const float*)d_in[0];
    const float* pred_boxes  = (const float*)d_in[1];
    const float* tgt_bbox    = (const float*)d_in[2];
    const int*   tgt_ids     = (const int*)d_in[3];
    float* out = (float*)d_out;

    class_kernel<<<NO / 2, 256>>>(pred_logits, tgt_ids, out);
    box_kernel<<<dim3(NT / 16, (NO + 15) / 16), 256>>>(
        (const float4*)pred_boxes, (const float4*)tgt_bbox, out);
}

// round 8
// speedup vs baseline: 1.0544x; 1.0544x over previous
#include <cuda_runtime.h>

#define NF 36
#define NO 1000
#define NT 256
#define NC 81

// ---------------------------------------------------------------------------
// A) Fused softmax + class cost (proven R5 version). Block owns 2 o's x 256 t.
//    9 rows/warp: all 27 scalar LDGs batched upfront, 9 SHFL chains
//    interleaved. Initializes d_out with class term + GIoU "+1" constant.
// ---------------------------------------------------------------------------
__global__ __launch_bounds__(256) void class_kernel(
    const float* __restrict__ logits,  // [F*O, C]
    const int*   __restrict__ tgt_ids, // [T*F]
    float*       __restrict__ out)     // [O, T]
{
    __shared__ float2 s_prob2[NF][NC];        // 23328 B
    __shared__ int    s_id4[NT][NF / 4];      // 9216 B

    const int ob   = blockIdx.x * 2;
    const int tid  = threadIdx.x;
    const int warp = tid >> 5;
    const int lane = tid & 31;

    // ---- batch-load all 9 rows this warp owns (27 LDGs in flight) ----
    float v[9][3];
    #pragma unroll
    for (int r = 0; r < 9; r++) {
        int row = warp + 8 * r;                 // 0..71
        int ol  = row / NF;
        int f   = row - ol * NF;
        const float* in = logits + (size_t)(f * NO + ob + ol) * NC;
        v[r][0] = in[lane];
        v[r][1] = in[lane + 32];
        v[r][2] = (lane < 17) ? in[lane + 64] : 0.0f;
    }

    // ---- exp (max-free: logits are O(1)) + per-row partial sums ----
    float s[9];
    #pragma unroll
    for (int r = 0; r < 9; r++) {
        float e0 = __expf(v[r][0]);
        float e1 = __expf(v[r][1]);
        float e2 = (lane < 17) ? __expf(v[r][2]) : 0.0f;
        v[r][0] = e0; v[r][1] = e1; v[r][2] = e2;
        s[r] = e0 + e1 + e2;
    }

    // ---- 9 independent SHFL chains, interleaved ----
    #pragma unroll
    for (int st = 16; st; st >>= 1) {
        #pragma unroll
        for (int r = 0; r < 9; r++)
            s[r] += __shfl_xor_sync(0xffffffffu, s[r], st);
    }

    // ---- normalize straight into interleaved SMEM ----
    #pragma unroll
    for (int r = 0; r < 9; r++) {
        float inv = __frcp_rn(s[r]);
        int row = warp + 8 * r;
        int ol  = row / NF;
        int f   = row - ol * NF;
        float* dst = (float*)&s_prob2[f][0] + ol;   // stride-2 interleave
        dst[2 * lane]        = v[r][0] * inv;
        dst[2 * (lane + 32)] = v[r][1] * inv;
        if (lane < 17) dst[2 * (lane + 64)] = v[r][2] * inv;
    }

    // ---- pack ids: 4 consecutive frames per int ----
    const int4* ids4 = (const int4*)tgt_ids;
    for (int i = tid; i < NT * NF / 4; i += 256) {
        int4 q = ids4[i];
        int t = i / (NF / 4);
        int p = i - t * (NF / 4);
        s_id4[t][p] = (q.x) | (q.y << 8) | (q.z << 16) | (q.w << 24);
    }
    __syncthreads();

    // ---- gather: one LDS.64 covers both o's ----
    const int t = tid;
    float a0 = 0.0f, a1 = 0.0f;
    #pragma unroll
    for (int fq = 0; fq < NF / 4; fq++) {
        int packed = s_id4[t][fq];
        #pragma unroll
        for (int b = 0; b < 4; b++) {
            int c = (packed >> (8 * b)) & 0xFF;
            float2 pr = s_prob2[fq * 4 + b][c];
            a0 += pr.x;
            a1 += pr.y;
        }
    }
    out[(ob + 0) * NT + t] = 1.0f - a0 * (1.0f / NF);
    out[(ob + 1) * NT + t] = 1.0f - a1 * (1.0f / NF);
}

// ---------------------------------------------------------------------------
// B) Box cost: 16 o x 16 t tiles, 1008 blocks, __launch_bounds__(256,7) ->
//    7 blocks/SM -> ALL blocks resident in one wave (1036 slots >= 1008),
//    occ ~87%, no tail. Warp = 16t x 2o with adjacent lanes sharing t
//    (T-tile LDS dedups to 16 addresses). No manual prefetch: 56 warps/SM
//    hide LDS latency; keeps regs <= 36.
// ---------------------------------------------------------------------------
__global__ __launch_bounds__(256, 7) void box_kernel(
    const float4* __restrict__ pred_boxes,   // [F, O] cxcywh
    const float4* __restrict__ tgt_bbox,     // [T, F] cxcywh
    float*        __restrict__ out)          // [O, T]
{
    __shared__ float4 s_pred[16][NF];    // xyxy 9216 B
    __shared__ float4 s_tgt[NF][16];     // xyxy 9216 B

    const int ob  = blockIdx.y * 16;
    const int tb  = blockIdx.x * 16;
    const int tid = threadIdx.x;

    for (int i = tid; i < 16 * NF; i += 256) {
        int ol = i & 15, f = i >> 4;
        int o  = min(ob + ol, NO - 1);            // clamp ragged last o-tile
        float4 b = pred_boxes[f * NO + o];
        s_pred[ol][f] = make_float4(b.x - 0.5f * b.z, b.y - 0.5f * b.w,
                                    b.x + 0.5f * b.z, b.y + 0.5f * b.w);
    }
    for (int i = tid; i < 16 * NF; i += 256) {
        int tl = i / NF, f = i - tl * NF;
        float4 b = tgt_bbox[(tb + tl) * NF + f];
        s_tgt[f][tl] = make_float4(b.x - 0.5f * b.z, b.y - 0.5f * b.w,
                                   b.x + 0.5f * b.z, b.y + 0.5f * b.w);
    }
    __syncthreads();

    const int lane = tid & 31;
    const int wid  = tid >> 5;
    const int op   = lane & 1;        // which of the warp's 2 o's
    const int tl   = lane >> 1;       // t within tile (adjacent lanes share)
    const int ol   = 2 * wid + op;    // o within tile

    float accG = 0.0f;   // sum over f of (inter/uni + uni/ca) == giou + 1
    float accC = 0.0f;   // |dx0+dx1| + |dy0+dy1|  (center terms, x2 scale)
    float accW = 0.0f;   // |dx1-dx0| + |dy1-dy0|  (w/h terms)

    #pragma unroll 4
    for (int f = 0; f < NF; f++) {
        float4 P = s_pred[ol][f];    // 2-address broadcast
        float4 T = s_tgt[f][tl];     // 16 distinct addrs -> 2 wavefronts

        float pw = P.z - P.x, ph = P.w - P.y;
        float tw = T.z - T.x, th = T.w - T.y;

        float iw = fminf(P.z, T.z) - fmaxf(P.x, T.x);
        float ih = fminf(P.w, T.w) - fmaxf(P.y, T.y);
        float inter = fmaxf(iw, 0.0f) * fmaxf(ih, 0.0f);
        float uni = fmaf(pw, ph, tw * th) - inter;
        float ca  = ((pw + tw) - iw) * ((ph + th) - ih);

        // inter/uni + uni/ca = (inter*ca + uni*uni) / (uni*ca)
        float r = __frcp_rn(uni * ca);
        accG = fmaf(fmaf(inter, ca, uni * uni), r, accG);

        float dx0 = P.x - T.x, dx1 = P.z - T.z;
        float dy0 = P.y - T.y, dy1 = P.w - T.w;
        accC += fabsf(dx0 + dx1) + fabsf(dy0 + dy1);
        accW += fabsf(dx1 - dx0) + fabsf(dy1 - dy0);
    }

    int o = ob + ol;
    int t = tb + tl;
    if (o < NO) {
        // bbox = (0.5*accC + accW)/(NF*4); giou "+1" folded into class init.
        out[o * NT + t] += (0.5f * accC + accW) * (1.0f / (NF * 4))
                           - accG * (1.0f / NF);
    }
}

// ---------------------------------------------------------------------------
extern "C" void kernel_launch(void* const* d_in, const int* in_sizes, int n_in,
                              void* d_out, int out_size) {
    const float* pred_logits = (const float*)d_in[0];
    const float* pred_boxes  = (const float*)d_in[1];
    const float* tgt_bbox    = (const float*)d_in[2];
    const int*   tgt_ids     = (const int*)d_in[3];
    float* out = (float*)d_out;

    class_kernel<<<NO / 2, 256>>>(pred_logits, tgt_ids, out);
    box_kernel<<<dim3(NT / 16, (NO + 15) / 16), 256>>>(
        (const float4*)pred_boxes, (const float4*)tgt_bbox, out);
}

// round 9
// speedup vs baseline: 1.0615x; 1.0067x over previous
#include <cuda_runtime.h>
#include <cstdint>

#define NF 36
#define NO 1000
#define NT 256
#define NC 81

// ---- packed f32x2 helpers (confirmed sm_103a PTX ops) ----------------------
#define ADD2(d, a, b) \
    asm("add.rn.f32x2 %0, %1, %2;" : "=l"(d) : "l"(a), "l"(b))
#define UNPACK2(lo, hi, v) \
    asm("mov.b64 {%0, %1}, %2;" : "=f"(lo), "=f"(hi) : "l"(v))
#define LDS_V2U64(lo, hi, addr) \
    asm volatile("ld.shared.v2.u64 {%0, %1}, [%2];" : "=l"(lo), "=l"(hi) : "r"(addr))
#define LDS_V4F32(v, addr) \
    asm volatile("ld.shared.v4.f32 {%0, %1, %2, %3}, [%4];" \
                 : "=f"(v.x), "=f"(v.y), "=f"(v.z), "=f"(v.w) : "r"(addr))

__device__ __forceinline__ uint32_t smem_u32(const void* p) {
    return (uint32_t)__cvta_generic_to_shared(p);
}

// ---------------------------------------------------------------------------
// A) Fused softmax + class cost (proven R5 version). Block owns 2 o's x 256 t.
//    Initializes d_out with class term + GIoU "+1" constant.
// ---------------------------------------------------------------------------
__global__ __launch_bounds__(256) void class_kernel(
    const float* __restrict__ logits,  // [F*O, C]
    const int*   __restrict__ tgt_ids, // [T*F]
    float*       __restrict__ out)     // [O, T]
{
    __shared__ float2 s_prob2[NF][NC];        // 23328 B
    __shared__ int    s_id4[NT][NF / 4];      // 9216 B

    const int ob   = blockIdx.x * 2;
    const int tid  = threadIdx.x;
    const int warp = tid >> 5;
    const int lane = tid & 31;

    // batch-load all 9 rows this warp owns (27 LDGs in flight)
    float v[9][3];
    #pragma unroll
    for (int r = 0; r < 9; r++) {
        int row = warp + 8 * r;                 // 0..71
        int ol  = row / NF;
        int f   = row - ol * NF;
        const float* in = logits + (size_t)(f * NO + ob + ol) * NC;
        v[r][0] = in[lane];
        v[r][1] = in[lane + 32];
        v[r][2] = (lane < 17) ? in[lane + 64] : 0.0f;
    }

    float s[9];
    #pragma unroll
    for (int r = 0; r < 9; r++) {
        float e0 = __expf(v[r][0]);
        float e1 = __expf(v[r][1]);
        float e2 = (lane < 17) ? __expf(v[r][2]) : 0.0f;
        v[r][0] = e0; v[r][1] = e1; v[r][2] = e2;
        s[r] = e0 + e1 + e2;
    }

    #pragma unroll
    for (int st = 16; st; st >>= 1) {
        #pragma unroll
        for (int r = 0; r < 9; r++)
            s[r] += __shfl_xor_sync(0xffffffffu, s[r], st);
    }

    #pragma unroll
    for (int r = 0; r < 9; r++) {
        float inv = __frcp_rn(s[r]);
        int row = warp + 8 * r;
        int ol  = row / NF;
        int f   = row - ol * NF;
        float* dst = (float*)&s_prob2[f][0] + ol;   // stride-2 interleave
        dst[2 * lane]        = v[r][0] * inv;
        dst[2 * (lane + 32)] = v[r][1] * inv;
        if (lane < 17) dst[2 * (lane + 64)] = v[r][2] * inv;
    }

    const int4* ids4 = (const int4*)tgt_ids;
    for (int i = tid; i < NT * NF / 4; i += 256) {
        int4 q = ids4[i];
        int t = i / (NF / 4);
        int p = i - t * (NF / 4);
        s_id4[t][p] = (q.x) | (q.y << 8) | (q.z << 16) | (q.w << 24);
    }
    __syncthreads();

    const int t = tid;
    float a0 = 0.0f, a1 = 0.0f;
    #pragma unroll
    for (int fq = 0; fq < NF / 4; fq++) {
        int packed = s_id4[t][fq];
        #pragma unroll
        for (int b = 0; b < 4; b++) {
            int c = (packed >> (8 * b)) & 0xFF;
            float2 pr = s_prob2[fq * 4 + b][c];
            a0 += pr.x;
            a1 += pr.y;
        }
    }
    out[(ob + 0) * NT + t] = 1.0f - a0 * (1.0f / NF);
    out[(ob + 1) * NT + t] = 1.0f - a1 * (1.0f / NF);
}

// ---------------------------------------------------------------------------
// B) Box cost: 16 o x 16 t tiles, warp = 16t x 2o (adjacent lanes share t).
//    SMEM: xyxy (for min/max) + cxcywh (pred) / NEGATED cxcywh (tgt).
//    L1 term fully packed in f32x2 (add.rn.f32x2 + one 64-bit abs mask);
//    (w,h) unpacked for free from the cxcywh register pair.
//    Manual prefetch of all 4 smem loads hides LDS latency.
// ---------------------------------------------------------------------------
__global__ __launch_bounds__(256) void box_kernel(
    const float4* __restrict__ pred_boxes,   // [F, O] cxcywh
    const float4* __restrict__ tgt_bbox,     // [T, F] cxcywh
    float*        __restrict__ out)          // [O, T]
{
    __shared__ float4 s_px[16][NF];    // pred xyxy            9216 B
    __shared__ float4 s_pc[16][NF];    // pred cxcywh          9216 B
    __shared__ float4 s_tx[NF][16];    // tgt xyxy             9216 B
    __shared__ float4 s_tc[NF][16];    // tgt cxcywh NEGATED   9216 B

    const int ob  = blockIdx.y * 16;
    const int tb  = blockIdx.x * 16;
    const int tid = threadIdx.x;

    for (int i = tid; i < 16 * NF; i += 256) {
        int ol = i & 15, f = i >> 4;
        int o  = min(ob + ol, NO - 1);            // clamp ragged last o-tile
        float4 b = pred_boxes[f * NO + o];
        s_pc[ol][f] = b;
        s_px[ol][f] = make_float4(b.x - 0.5f * b.z, b.y - 0.5f * b.w,
                                  b.x + 0.5f * b.z, b.y + 0.5f * b.w);
    }
    for (int i = tid; i < 16 * NF; i += 256) {
        int tl = i / NF, f = i - tl * NF;
        float4 b = tgt_bbox[(tb + tl) * NF + f];
        s_tc[f][tl] = make_float4(-b.x, -b.y, -b.z, -b.w);
        s_tx[f][tl] = make_float4(b.x - 0.5f * b.z, b.y - 0.5f * b.w,
                                  b.x + 0.5f * b.z, b.y + 0.5f * b.w);
    }
    __syncthreads();

    const int lane = tid & 31;
    const int wid  = tid >> 5;
    const int op   = lane & 1;        // which of the warp's 2 o's
    const int tl   = lane >> 1;       // t within tile (adjacent lanes share)
    const int ol   = 2 * wid + op;    // o within tile

    // shared-space byte addresses (stride per f: pred 16B, tgt 256B)
    uint32_t a_px = smem_u32(&s_px[ol][0]);
    uint32_t a_pc = smem_u32(&s_pc[ol][0]);
    uint32_t a_tx = smem_u32(&s_tx[0][tl]);
    uint32_t a_tc = smem_u32(&s_tc[0][tl]);

    float    accG  = 0.0f;           // sum (inter/uni + uni/ca) == giou + 1
    uint64_t accC2 = 0, accW2 = 0;   // packed |d(cx,cy)|, |d(w,h)| sums

    float4   P, T;
    uint64_t Pc, Pwh, nTc, nTwh;
    LDS_V4F32(P, a_px);
    LDS_V4F32(T, a_tx);
    LDS_V2U64(Pc, Pwh, a_pc);
    LDS_V2U64(nTc, nTwh, a_tc);

    #pragma unroll 4
    for (int f = 0; f < NF; f++) {
        float4   Pn, Tn;
        uint64_t Pcn, Pwhn, nTcn, nTwhn;
        if (f < NF - 1) {
            LDS_V4F32(Pn, a_px + (f + 1) * 16);
            LDS_V4F32(Tn, a_tx + (f + 1) * 256);
            LDS_V2U64(Pcn, Pwhn, a_pc + (f + 1) * 16);
            LDS_V2U64(nTcn, nTwhn, a_tc + (f + 1) * 256);
        }

        float pw, ph, ntw, nth;
        UNPACK2(pw, ph, Pwh);       // register-pair aliasing, no real MOV
        UNPACK2(ntw, nth, nTwh);

        float iw = fminf(P.z, T.z) - fmaxf(P.x, T.x);
        float ih = fminf(P.w, T.w) - fmaxf(P.y, T.y);
        float inter = fmaxf(iw, 0.0f) * fmaxf(ih, 0.0f);
        float uni = fmaf(pw, ph, ntw * nth) - inter;   // (-tw)*(-th) = tw*th
        float cw  = (pw - ntw) - iw;                   // pw + tw - iw
        float ch  = (ph - nth) - ih;
        float ca  = cw * ch;

        // inter/uni + uni/ca = (inter*ca + uni*uni) / (uni*ca)
        float r = __frcp_rn(uni * ca);
        accG = fmaf(fmaf(inter, ca, uni * uni), r, accG);

        // packed L1: d = P + (-T) for (cx,cy) and (w,h)
        uint64_t dc, dwh;
        ADD2(dc,  Pc,  nTc);
        ADD2(dwh, Pwh, nTwh);
        dc  &= 0x7FFFFFFF7FFFFFFFull;   // packed fabs (2x LOP3, alu pipe)
        dwh &= 0x7FFFFFFF7FFFFFFFull;
        ADD2(accC2, accC2, dc);
        ADD2(accW2, accW2, dwh);

        P = Pn; T = Tn;
        Pc = Pcn; Pwh = Pwhn; nTc = nTcn; nTwh = nTwhn;
    }

    int o = ob + ol;
    int t = tb + tl;
    if (o < NO) {
        float c0, c1, w0, w1;
        UNPACK2(c0, c1, accC2);
        UNPACK2(w0, w1, accW2);
        float bbox = (c0 + c1 + w0 + w1) * (1.0f / (NF * 4));
        // giou "+1" constant folded into class_kernel's init
        out[o * NT + t] += bbox - accG * (1.0f / NF);
    }
}

// ---------------------------------------------------------------------------
extern "C" void kernel_launch(void* const* d_in, const int* in_sizes, int n_in,
                              void* d_out, int out_size) {
    const float* pred_logits = (const float*)d_in[0];
    const float* pred_boxes  = (const float*)d_in[1];
    const float* tgt_bbox    = (const float*)d_in[2];
    const int*   tgt_ids     = (const int*)d_in[3];
    float* out = (float*)d_out;

    class_kernel<<<NO / 2, 256>>>(pred_logits, tgt_ids, out);
    box_kernel<<<dim3(NT / 16, (NO + 15) / 16), 256>>>(
        (const float4*)pred_boxes, (const float4*)tgt_bbox, out);
}

// round 10
// speedup vs baseline: 1.1548x; 1.0879x over previous
#include <cuda_runtime.h>

#define NF 36
#define NO 1000
#define NT 256
#define NC 81

// ---------------------------------------------------------------------------
// A) Fused softmax + class cost (proven R5 version). Block owns 2 o's x 256 t.
//    Initializes d_out with class term + GIoU "+1" constant.
//    Triggers programmatic launch completion immediately so the box kernel's
//    blocks can co-schedule onto the SMs this grid leaves idle.
// ---------------------------------------------------------------------------
__global__ __launch_bounds__(256) void class_kernel(
    const float* __restrict__ logits,  // [F*O, C]
    const int*   __restrict__ tgt_ids, // [T*F]
    float*       __restrict__ out)     // [O, T]
{
    if (threadIdx.x == 0) cudaTriggerProgrammaticLaunchCompletion();

    __shared__ float2 s_prob2[NF][NC];        // 23328 B
    __shared__ int    s_id4[NT][NF / 4];      // 9216 B

    const int ob   = blockIdx.x * 2;
    const int tid  = threadIdx.x;
    const int warp = tid >> 5;
    const int lane = tid & 31;

    // ---- batch-load all 9 rows this warp owns (27 LDGs in flight) ----
    float v[9][3];
    #pragma unroll
    for (int r = 0; r < 9; r++) {
        int row = warp + 8 * r;                 // 0..71
        int ol  = row / NF;
        int f   = row - ol * NF;
        const float* in = logits + (size_t)(f * NO + ob + ol) * NC;
        v[r][0] = in[lane];
        v[r][1] = in[lane + 32];
        v[r][2] = (lane < 17) ? in[lane + 64] : 0.0f;
    }

    // ---- exp (max-free: logits are O(1)) + per-row partial sums ----
    float s[9];
    #pragma unroll
    for (int r = 0; r < 9; r++) {
        float e0 = __expf(v[r][0]);
        float e1 = __expf(v[r][1]);
        float e2 = (lane < 17) ? __expf(v[r][2]) : 0.0f;
        v[r][0] = e0; v[r][1] = e1; v[r][2] = e2;
        s[r] = e0 + e1 + e2;
    }

    // ---- 9 independent SHFL chains, interleaved ----
    #pragma unroll
    for (int st = 16; st; st >>= 1) {
        #pragma unroll
        for (int r = 0; r < 9; r++)
            s[r] += __shfl_xor_sync(0xffffffffu, s[r], st);
    }

    // ---- normalize straight into interleaved SMEM ----
    #pragma unroll
    for (int r = 0; r < 9; r++) {
        float inv = __frcp_rn(s[r]);
        int row = warp + 8 * r;
        int ol  = row / NF;
        int f   = row - ol * NF;
        float* dst = (float*)&s_prob2[f][0] + ol;   // stride-2 interleave
        dst[2 * lane]        = v[r][0] * inv;
        dst[2 * (lane + 32)] = v[r][1] * inv;
        if (lane < 17) dst[2 * (lane + 64)] = v[r][2] * inv;
    }

    // ---- pack ids: 4 consecutive frames per int ----
    const int4* ids4 = (const int4*)tgt_ids;
    for (int i = tid; i < NT * NF / 4; i += 256) {
        int4 q = ids4[i];
        int t = i / (NF / 4);
        int p = i - t * (NF / 4);
        s_id4[t][p] = (q.x) | (q.y << 8) | (q.z << 16) | (q.w << 24);
    }
    __syncthreads();

    // ---- gather: one LDS.64 covers both o's ----
    const int t = tid;
    float a0 = 0.0f, a1 = 0.0f;
    #pragma unroll
    for (int fq = 0; fq < NF / 4; fq++) {
        int packed = s_id4[t][fq];
        #pragma unroll
        for (int b = 0; b < 4; b++) {
            int c = (packed >> (8 * b)) & 0xFF;
            float2 pr = s_prob2[fq * 4 + b][c];
            a0 += pr.x;
            a1 += pr.y;
        }
    }
    out[(ob + 0) * NT + t] = 1.0f - a0 * (1.0f / NF);
    out[(ob + 1) * NT + t] = 1.0f - a1 * (1.0f / NF);
}

// ---------------------------------------------------------------------------
// B) Box cost (best-measured R6 body): 16 o x 16 t tiles, warp = 16t x 2o
//    (adjacent lanes share t -> T-tile LDS dedups to 16 addresses), xyxy-only
//    smem, manual prefetch. Launched with programmatic stream serialization:
//    all heavy work overlaps class_kernel; cudaGridDependencySynchronize()
//    gates only the final += on out.
// ---------------------------------------------------------------------------
__global__ __launch_bounds__(256) void box_kernel(
    const float4* __restrict__ pred_boxes,   // [F, O] cxcywh
    const float4* __restrict__ tgt_bbox,     // [T, F] cxcywh
    float*        __restrict__ out)          // [O, T]
{
    __shared__ float4 s_pred[16][NF];    // xyxy 9216 B
    __shared__ float4 s_tgt[NF][16];     // xyxy 9216 B

    const int ob  = blockIdx.y * 16;
    const int tb  = blockIdx.x * 16;
    const int tid = threadIdx.x;

    for (int i = tid; i < 16 * NF; i += 256) {
        int ol = i & 15, f = i >> 4;
        int o  = min(ob + ol, NO - 1);            // clamp ragged last o-tile
        float4 b = pred_boxes[f * NO + o];
        s_pred[ol][f] = make_float4(b.x - 0.5f * b.z, b.y - 0.5f * b.w,
                                    b.x + 0.5f * b.z, b.y + 0.5f * b.w);
    }
    for (int i = tid; i < 16 * NF; i += 256) {
        int tl = i / NF, f = i - tl * NF;
        float4 b = tgt_bbox[(tb + tl) * NF + f];
        s_tgt[f][tl] = make_float4(b.x - 0.5f * b.z, b.y - 0.5f * b.w,
                                   b.x + 0.5f * b.z, b.y + 0.5f * b.w);
    }
    __syncthreads();

    const int lane = tid & 31;
    const int wid  = tid >> 5;
    const int op   = lane & 1;        // which of the warp's 2 o's
    const int tl   = lane >> 1;       // t within tile (adjacent lanes share)
    const int ol   = 2 * wid + op;    // o within tile

    float accG = 0.0f;   // sum over f of (inter/uni + uni/ca) == giou + 1
    float accC = 0.0f;   // |dx0+dx1| + |dy0+dy1|  (center terms, x2 scale)
    float accW = 0.0f;   // |dx1-dx0| + |dy1-dy0|  (w/h terms)

    float4 P = s_pred[ol][0];
    float4 T = s_tgt[0][tl];

    #pragma unroll 4
    for (int f = 0; f < NF; f++) {
        float4 Pn, Tn;
        if (f < NF - 1) {                 // prefetch next frame
            Pn = s_pred[ol][f + 1];
            Tn = s_tgt[f + 1][tl];
        }

        float pw = P.z - P.x, ph = P.w - P.y;
        float tw = T.z - T.x, th = T.w - T.y;

        float iw = fminf(P.z, T.z) - fmaxf(P.x, T.x);
        float ih = fminf(P.w, T.w) - fmaxf(P.y, T.y);
        float inter = fmaxf(iw, 0.0f) * fmaxf(ih, 0.0f);
        float uni = fmaf(pw, ph, tw * th) - inter;
        float ca  = ((pw + tw) - iw) * ((ph + th) - ih);

        // inter/uni + uni/ca = (inter*ca + uni*uni) / (uni*ca)
        float r = __frcp_rn(uni * ca);
        accG = fmaf(fmaf(inter, ca, uni * uni), r, accG);

        float dx0 = P.x - T.x, dx1 = P.z - T.z;
        float dy0 = P.y - T.y, dy1 = P.w - T.w;
        accC += fabsf(dx0 + dx1) + fabsf(dy0 + dy1);
        accW += fabsf(dx1 - dx0) + fabsf(dy1 - dy0);

        P = Pn; T = Tn;
    }

    // Wait for class_kernel's writes to `out` to be visible, then accumulate.
    cudaGridDependencySynchronize();

    int o = ob + ol;
    int t = tb + tl;
    if (o < NO) {
        // bbox = (0.5*accC + accW)/(NF*4); giou "+1" folded into class init.
        out[o * NT + t] += (0.5f * accC + accW) * (1.0f / (NF * 4))
                           - accG * (1.0f / NF);
    }
}

// ---------------------------------------------------------------------------
extern "C" void kernel_launch(void* const* d_in, const int* in_sizes, int n_in,
                              void* d_out, int out_size) {
    const float* pred_logits = (const float*)d_in[0];
    const float* pred_boxes  = (const float*)d_in[1];
    const float* tgt_bbox    = (const float*)d_in[2];
    const int*   tgt_ids     = (const int*)d_in[3];
    float* out = (float*)d_out;

    class_kernel<<<NO / 2, 256>>>(pred_logits, tgt_ids, out);

    // Box kernel with Programmatic Dependent Launch: starts while class_kernel
    // is still running; its gridDependencySynchronize orders the out += .
    cudaLaunchConfig_t cfg = {};
    cfg.gridDim  = dim3(NT / 16, (NO + 15) / 16, 1);
    cfg.blockDim = dim3(256, 1, 1);
    cfg.dynamicSmemBytes = 0;
    cfg.stream = 0;
    cudaLaunchAttribute attr[1];
    attr[0].id = cudaLaunchAttributeProgrammaticStreamSerialization;
    attr[0].val.programmaticStreamSerializationAllowed = 1;
    cfg.attrs = attr;
    cfg.numAttrs = 1;
    cudaLaunchKernelEx(&cfg, box_kernel,
                       (const float4*)pred_boxes, (const float4*)tgt_bbox, out);
}

// round 11
// speedup vs baseline: 1.2105x; 1.0482x over previous
#include <cuda_runtime.h>

#define NF 36
#define NO 1000
#define NT 256
#define NC 81

// ---------------------------------------------------------------------------
// A) Fused softmax + class cost. Block owns 2 o's x 256 t, 512 THREADS:
//    16 warps share the 72 softmax rows (~4.5 rows/warp, half the serial
//    chain of the 8-warp version); the gather phase is split across thread
//    halves (frames 0-15 / 16-35) and combined through smem.
//    Initializes d_out with class term + GIoU "+1" constant.
//    Triggers programmatic launch completion immediately so box_kernel
//    co-schedules onto idle slots.
// ---------------------------------------------------------------------------
__global__ __launch_bounds__(512) void class_kernel(
    const float* __restrict__ logits,  // [F*O, C]
    const int*   __restrict__ tgt_ids, // [T*F]
    float*       __restrict__ out)     // [O, T]
{
    if (threadIdx.x == 0) cudaTriggerProgrammaticLaunchCompletion();

    __shared__ float2 s_prob2[NF][NC];        // 23328 B
    __shared__ int    s_id4[NT][NF / 4];      // 9216 B
    __shared__ float2 s_part[NT];             // 2048 B

    const int ob   = blockIdx.x * 2;
    const int tid  = threadIdx.x;
    const int warp = tid >> 5;                // 0..15
    const int lane = tid & 31;

    // ---- batch-load this warp's rows (up to 5 of 72; 15 LDGs in flight) ----
    float v[5][3];
    float s[5];
    #pragma unroll
    for (int k = 0; k < 5; k++) {
        int r = warp + 16 * k;                // 0..79, valid < 72
        if (r < 2 * NF) {
            int ol = r / NF;
            int f  = r - ol * NF;
            const float* in = logits + (size_t)(f * NO + ob + ol) * NC;
            v[k][0] = in[lane];
            v[k][1] = in[lane + 32];
            v[k][2] = (lane < 17) ? in[lane + 64] : 0.0f;
        } else {
            v[k][0] = v[k][1] = v[k][2] = 0.0f;
        }
    }

    // ---- exp (max-free: logits are O(1)) + per-row partial sums ----
    #pragma unroll
    for (int k = 0; k < 5; k++) {
        float e0 = __expf(v[k][0]);
        float e1 = __expf(v[k][1]);
        float e2 = (lane < 17) ? __expf(v[k][2]) : 0.0f;
        v[k][0] = e0; v[k][1] = e1; v[k][2] = e2;
        s[k] = e0 + e1 + e2;
    }

    // ---- 5 independent SHFL chains, interleaved ----
    #pragma unroll
    for (int st = 16; st; st >>= 1) {
        #pragma unroll
        for (int k = 0; k < 5; k++)
            s[k] += __shfl_xor_sync(0xffffffffu, s[k], st);
    }

    // ---- normalize straight into interleaved SMEM ----
    #pragma unroll
    for (int k = 0; k < 5; k++) {
        int r = warp + 16 * k;
        if (r < 2 * NF) {
            float inv = __frcp_rn(s[k]);
            int ol = r / NF;
            int f  = r - ol * NF;
            float* dst = (float*)&s_prob2[f][0] + ol;   // stride-2 interleave
            dst[2 * lane]        = v[k][0] * inv;
            dst[2 * (lane + 32)] = v[k][1] * inv;
            if (lane < 17) dst[2 * (lane + 64)] = v[k][2] * inv;
        }
    }

    // ---- pack ids: 4 consecutive frames per int ----
    const int4* ids4 = (const int4*)tgt_ids;
    for (int i = tid; i < NT * NF / 4; i += 512) {
        int4 q = ids4[i];
        int t = i / (NF / 4);
        int p = i - t * (NF / 4);
        s_id4[t][p] = (q.x) | (q.y << 8) | (q.z << 16) | (q.w << 24);
    }
    __syncthreads();

    // ---- gather, split across thread halves: fq 0..3 / fq 4..8 ----
    const int t    = tid & (NT - 1);
    const int half = tid >> 8;          // 0 or 1
    const int fq0  = half ? 4 : 0;
    const int fq1  = half ? 9 : 4;

    float a0 = 0.0f, a1 = 0.0f;
    #pragma unroll
    for (int fq = fq0; fq < fq1; fq++) {
        int packed = s_id4[t][fq];
        #pragma unroll
        for (int b = 0; b < 4; b++) {
            int c = (packed >> (8 * b)) & 0xFF;
            float2 pr = s_prob2[fq * 4 + b][c];
            a0 += pr.x;
            a1 += pr.y;
        }
    }
    if (half) s_part[t] = make_float2(a0, a1);
    __syncthreads();
    if (!half) {
        float2 p = s_part[t];
        a0 += p.x;
        a1 += p.y;
        out[(ob + 0) * NT + t] = 1.0f - a0 * (1.0f / NF);
        out[(ob + 1) * NT + t] = 1.0f - a1 * (1.0f / NF);
    }
}

// ---------------------------------------------------------------------------
// B) Box cost (best-measured R6 body, unchanged): 16 o x 16 t tiles,
//    warp = 16t x 2o (adjacent lanes share t), xyxy-only smem, manual
//    prefetch. PDL: compute overlaps class_kernel; gridDependencySynchronize
//    gates only the final += on out.
// ---------------------------------------------------------------------------
__global__ __launch_bounds__(256) void box_kernel(
    const float4* __restrict__ pred_boxes,   // [F, O] cxcywh
    const float4* __restrict__ tgt_bbox,     // [T, F] cxcywh
    float*        __restrict__ out)          // [O, T]
{
    __shared__ float4 s_pred[16][NF];    // xyxy 9216 B
    __shared__ float4 s_tgt[NF][16];     // xyxy 9216 B

    const int ob  = blockIdx.y * 16;
    const int tb  = blockIdx.x * 16;
    const int tid = threadIdx.x;

    for (int i = tid; i < 16 * NF; i += 256) {
        int ol = i & 15, f = i >> 4;
        int o  = min(ob + ol, NO - 1);            // clamp ragged last o-tile
        float4 b = pred_boxes[f * NO + o];
        s_pred[ol][f] = make_float4(b.x - 0.5f * b.z, b.y - 0.5f * b.w,
                                    b.x + 0.5f * b.z, b.y + 0.5f * b.w);
    }
    for (int i = tid; i < 16 * NF; i += 256) {
        int tl = i / NF, f = i - tl * NF;
        float4 b = tgt_bbox[(tb + tl) * NF + f];
        s_tgt[f][tl] = make_float4(b.x - 0.5f * b.z, b.y - 0.5f * b.w,
                                   b.x + 0.5f * b.z, b.y + 0.5f * b.w);
    }
    __syncthreads();

    const int lane = tid & 31;
    const int wid  = tid >> 5;
    const int op   = lane & 1;        // which of the warp's 2 o's
    const int tl   = lane >> 1;       // t within tile (adjacent lanes share)
    const int ol   = 2 * wid + op;    // o within tile

    float accG = 0.0f;   // sum over f of (inter/uni + uni/ca) == giou + 1
    float accC = 0.0f;   // |dx0+dx1| + |dy0+dy1|  (center terms, x2 scale)
    float accW = 0.0f;   // |dx1-dx0| + |dy1-dy0|  (w/h terms)

    float4 P = s_pred[ol][0];
    float4 T = s_tgt[0][tl];

    #pragma unroll 4
    for (int f = 0; f < NF; f++) {
        float4 Pn, Tn;
        if (f < NF - 1) {                 // prefetch next frame
            Pn = s_pred[ol][f + 1];
            Tn = s_tgt[f + 1][tl];
        }

        float pw = P.z - P.x, ph = P.w - P.y;
        float tw = T.z - T.x, th = T.w - T.y;

        float iw = fminf(P.z, T.z) - fmaxf(P.x, T.x);
        float ih = fminf(P.w, T.w) - fmaxf(P.y, T.y);
        float inter = fmaxf(iw, 0.0f) * fmaxf(ih, 0.0f);
        float uni = fmaf(pw, ph, tw * th) - inter;
        float ca  = ((pw + tw) - iw) * ((ph + th) - ih);

        // inter/uni + uni/ca = (inter*ca + uni*uni) / (uni*ca)
        float r = __frcp_rn(uni * ca);
        accG = fmaf(fmaf(inter, ca, uni * uni), r, accG);

        float dx0 = P.x - T.x, dx1 = P.z - T.z;
        float dy0 = P.y - T.y, dy1 = P.w - T.w;
        accC += fabsf(dx0 + dx1) + fabsf(dy0 + dy1);
        accW += fabsf(dx1 - dx0) + fabsf(dy1 - dy0);

        P = Pn; T = Tn;
    }

    // Wait for class_kernel's writes to `out` to be visible, then accumulate.
    cudaGridDependencySynchronize();

    int o = ob + ol;
    int t = tb + tl;
    if (o < NO) {
        // bbox = (0.5*accC + accW)/(NF*4); giou "+1" folded into class init.
        out[o * NT + t] += (0.5f * accC + accW) * (1.0f / (NF * 4))
                           - accG * (1.0f / NF);
    }
}

// ---------------------------------------------------------------------------
extern "C" void kernel_launch(void* const* d_in, const int* in_sizes, int n_in,
                              void* d_out, int out_size) {
    const float* pred_logits = (const float*)d_in[0];
    const float* pred_boxes  = (const float*)d_in[1];
    const float* tgt_bbox    = (const float*)d_in[2];
    const int*   tgt_ids     = (const int*)d_in[3];
    float* out = (float*)d_out;

    class_kernel<<<NO / 2, 512>>>(pred_logits, tgt_ids, out);

    // Box kernel with Programmatic Dependent Launch: starts while class_kernel
    // is still running; its gridDependencySynchronize orders the out += .
    cudaLaunchConfig_t cfg = {};
    cfg.gridDim  = dim3(NT / 16, (NO + 15) / 16, 1);
    cfg.blockDim = dim3(256, 1, 1);
    cfg.dynamicSmemBytes = 0;
    cfg.stream = 0;
    cudaLaunchAttribute attr[1];
    attr[0].id = cudaLaunchAttributeProgrammaticStreamSerialization;
    attr[0].val.programmaticStreamSerializationAllowed = 1;
    cfg.attrs = attr;
    cfg.numAttrs = 1;
    cudaLaunchKernelEx(&cfg, box_kernel,
                       (const float4*)pred_boxes, (const float4*)tgt_bbox, out);
}